// round 9
// baseline (speedup 1.0000x reference)
#include <cuda_runtime.h>
#include <math.h>

// MaskedLightAdaIN, three-pass pipeline with bit-packed mask:
//   0) pack_kernel:     mask f32 [16,1,256,256] -> 1 bit/pixel (128 KB total)
//   1) stats_kernel:    per quarter-plane partial sums (fixed slots, no atomics)
//   2) finalize_kernel: combine 4 slots/plane -> scale/bias (deterministic)
//   3) apply_kernel:    out = fg ? x : x*scale+bias, streaming loads/stores
// Bit-packing removes the 64x-per-batch mask re-read that saturated L2.

#define NB      16
#define NBC     1024            // planes (B*C)
#define HW      65536
#define HW4     16384           // float4 per plane
#define Q4      4096            // float4 per quarter plane
#define PMW     2048            // uint32 words per batch (HW/32)
#define EPSV    1e-8f

__device__ unsigned g_pm[NB][PMW];    // packed mask: bit j of word w = pixel w*32+j
__device__ float    g_part[NBC][4][5];
__device__ float2   g_sb[NBC];

// ---------------------------------------------------------------------------
// Pass 0: bit-pack the mask. One thread per uint32 word (32 pixels).
// ---------------------------------------------------------------------------
__global__ void __launch_bounds__(256) pack_kernel(const float* __restrict__ mask)
{
    const int w  = blockIdx.x * 256 + threadIdx.x;   // 0..32767
    const int b  = w >> 11;
    const int wi = w & (PMW - 1);

    const float4* __restrict__ mp = reinterpret_cast<const float4*>(mask)
                                  + (size_t)b * HW4 + wi * 8;
    unsigned bits = 0;
    #pragma unroll
    for (int k = 0; k < 8; k++) {
        float4 mv = __ldcs(&mp[k]);
        unsigned nib = (mv.x >= 0.5f) | ((mv.y >= 0.5f) << 1)
                     | ((mv.z >= 0.5f) << 2) | ((mv.w >= 0.5f) << 3);
        bits |= nib << (4 * k);
    }
    g_pm[b][wi] = bits;
}

// ---------------------------------------------------------------------------
// Pass 1: partial sums per quarter-plane. 256 threads x 16 float4.
// ---------------------------------------------------------------------------
__global__ void __launch_bounds__(256) stats_kernel(const float* __restrict__ x)
{
    const int blk = blockIdx.x;         // 0..4095
    const int p   = blk >> 2;           // plane
    const int q   = blk & 3;            // quarter
    const int b   = p >> 6;             // batch

    const float4* __restrict__ xp = reinterpret_cast<const float4*>(x)
                                  + (size_t)p * HW4 + q * Q4;
    const unsigned* __restrict__ pm = &g_pm[b][0];
    const int fbase = q * Q4;           // float4 index base within plane

    float s_all = 0.f, q_all = 0.f, s_fg = 0.f, q_fg = 0.f;
    int   n_cnt = 0;

    #pragma unroll 4
    for (int k = 0; k < 16; k++) {
        const int i = threadIdx.x + (k << 8);
        float4 xv = __ldcs(&xp[i]);
        const int f = fbase + i;
        unsigned nib = (pm[f >> 3] >> ((f & 7) * 4)) & 0xFu;

        float x0 = xv.x, x1 = xv.y, x2 = xv.z, x3 = xv.w;
        float q0 = x0*x0, q1 = x1*x1, q2 = x2*x2, q3 = x3*x3;

        s_all += x0 + x1 + x2 + x3;
        q_all += q0 + q1 + q2 + q3;
        if (nib & 1u) { s_fg += x0; q_fg += q0; }
        if (nib & 2u) { s_fg += x1; q_fg += q1; }
        if (nib & 4u) { s_fg += x2; q_fg += q2; }
        if (nib & 8u) { s_fg += x3; q_fg += q3; }
        n_cnt += __popc(nib);
    }
    float n_fg = (float)n_cnt;

    #pragma unroll
    for (int o = 16; o > 0; o >>= 1) {
        s_all += __shfl_xor_sync(0xffffffffu, s_all, o);
        q_all += __shfl_xor_sync(0xffffffffu, q_all, o);
        s_fg  += __shfl_xor_sync(0xffffffffu, s_fg,  o);
        q_fg  += __shfl_xor_sync(0xffffffffu, q_fg,  o);
        n_fg  += __shfl_xor_sync(0xffffffffu, n_fg,  o);
    }

    __shared__ float red[8][5];
    const int warp = threadIdx.x >> 5;
    const int lane = threadIdx.x & 31;
    if (lane == 0) {
        red[warp][0] = s_all; red[warp][1] = q_all;
        red[warp][2] = s_fg;  red[warp][3] = q_fg;
        red[warp][4] = n_fg;
    }
    __syncthreads();

    if (threadIdx.x < 32) {
        float v0 = (lane < 8) ? red[lane][0] : 0.f;
        float v1 = (lane < 8) ? red[lane][1] : 0.f;
        float v2 = (lane < 8) ? red[lane][2] : 0.f;
        float v3 = (lane < 8) ? red[lane][3] : 0.f;
        float v4 = (lane < 8) ? red[lane][4] : 0.f;
        #pragma unroll
        for (int o = 4; o > 0; o >>= 1) {
            v0 += __shfl_xor_sync(0xffffffffu, v0, o);
            v1 += __shfl_xor_sync(0xffffffffu, v1, o);
            v2 += __shfl_xor_sync(0xffffffffu, v2, o);
            v3 += __shfl_xor_sync(0xffffffffu, v3, o);
            v4 += __shfl_xor_sync(0xffffffffu, v4, o);
        }
        if (lane == 0) {
            g_part[p][q][0] = v0;
            g_part[p][q][1] = v1;
            g_part[p][q][2] = v2;
            g_part[p][q][3] = v3;
            g_part[p][q][4] = v4;
        }
    }
}

// ---------------------------------------------------------------------------
// Pass 2: combine quarter slots (fixed order -> bit-deterministic)
// ---------------------------------------------------------------------------
__global__ void finalize_kernel()
{
    const int p = blockIdx.x * blockDim.x + threadIdx.x;
    if (p >= NBC) return;

    float t0 = 0.f, t1 = 0.f, t2 = 0.f, t3 = 0.f, nf = 0.f;
    #pragma unroll
    for (int s = 0; s < 4; s++) {
        t0 += g_part[p][s][0];
        t1 += g_part[p][s][1];
        t2 += g_part[p][s][2];
        t3 += g_part[p][s][3];
        nf += g_part[p][s][4];
    }
    float nb  = (float)HW - nf;
    float s_b = t0 - t2, q_b = t1 - t3;

    float mu_f  = t2 / nf;
    float var_f = fmaxf(t3 - t2 * mu_f, 0.f) / (nf - 1.f);
    float sig_f = sqrtf(var_f);

    float mu_b  = s_b / nb;
    float var_b = fmaxf(q_b - s_b * mu_b, 0.f) / (nb - 1.f);
    float sig_b = sqrtf(var_b);

    float scale = sig_f / (sig_b + EPSV);
    float bias  = mu_f - mu_b * scale;
    g_sb[p] = make_float2(scale, bias);
}

// ---------------------------------------------------------------------------
// Pass 3: elementwise apply using packed mask bits.
// ---------------------------------------------------------------------------
__global__ void __launch_bounds__(256) apply_kernel(const float* __restrict__ x,
                                                    float* __restrict__ out)
{
    const int blk = blockIdx.x;         // 0..16383
    const int p   = blk >> 4;           // plane
    const int seg = blk & 15;           // 1024-float4 segment
    const int b   = p >> 6;

    const size_t xoff = (size_t)p * HW4 + (size_t)seg * 1024;
    const float4* __restrict__ xp = reinterpret_cast<const float4*>(x) + xoff;
    float4*       __restrict__ op = reinterpret_cast<float4*>(out)     + xoff;
    const unsigned* __restrict__ pm = &g_pm[b][0];
    const int fbase = seg * 1024;

    const float2 sb = g_sb[p];
    const float scale = sb.x;
    const float bias  = sb.y;

    #pragma unroll
    for (int k = 0; k < 4; k++) {
        const int i = threadIdx.x + (k << 8);
        float4 xv = __ldcs(&xp[i]);
        const int f = fbase + i;
        unsigned nib = (pm[f >> 3] >> ((f & 7) * 4)) & 0xFu;

        float4 ov;
        ov.x = (nib & 1u) ? xv.x : fmaf(xv.x, scale, bias);
        ov.y = (nib & 2u) ? xv.y : fmaf(xv.y, scale, bias);
        ov.z = (nib & 4u) ? xv.z : fmaf(xv.z, scale, bias);
        ov.w = (nib & 8u) ? xv.w : fmaf(xv.w, scale, bias);

        __stcs(&op[i], ov);
    }
}

extern "C" void kernel_launch(void* const* d_in, const int* in_sizes, int n_in,
                              void* d_out, int out_size)
{
    const float* x    = (const float*)d_in[0];
    const float* mask = (const float*)d_in[1];
    float* out        = (float*)d_out;

    pack_kernel<<<128, 256>>>(mask);
    stats_kernel<<<4 * NBC, 256>>>(x);
    finalize_kernel<<<4, 256>>>();
    apply_kernel<<<16 * NBC, 256>>>(x, out);
}